// round 10
// baseline (speedup 1.0000x reference)
#include <cuda_runtime.h>
#include <cuda_fp16.h>
#include <cstdint>

#define ROWS 8192
#define KDIM 128
#define NPER 82          // int(8192 * 1 / 100) + 1
#define EPS  1.25e-3f    // certified |dot_hh - dot| bound coeff (x ||a||*||b||)
#define EPS2 3.0e-5f     // level-2 window after smem correction (x ||a||*||b||)
#define QCAP 1024

// Scratch (device globals: no allocation allowed)
__device__ float  g_r[ROWS];            // dot(x1_i, x2_i) / ||x2_i||
__device__ float  g_n1[ROWS];           // ||x1_i||
__device__ float  g_n2[ROWS];           // ||x2_j||
__device__ int    g_cnt[ROWS];          // per-row count of strictly-greater sims
__device__ __half g_x1h[ROWS * KDIM];   // fp16 hi/lo split of inputs
__device__ __half g_x1l[ROWS * KDIM];
__device__ __half g_x2h[ROWS * KDIM];
__device__ __half g_x2l[ROWS * KDIM];

__device__ __forceinline__ uint32_t smem_u32(const void* p) {
    uint32_t a;
    asm("{ .reg .u64 t; cvta.to.shared.u64 t, %1; cvt.u32.u64 %0, t; }"
        : "=r"(a) : "l"(p));
    return a;
}

#define LDSM_X4(r0, r1, r2, r3, addr) \
    asm volatile("ldmatrix.sync.aligned.m8n8.x4.shared.b16 {%0,%1,%2,%3}, [%4];" \
                 : "=r"(r0), "=r"(r1), "=r"(r2), "=r"(r3) : "r"(addr))

#define MMA_16816(c, a, b0, b1) \
    asm volatile("mma.sync.aligned.m16n8k16.row.col.f32.f16.f16.f32 " \
                 "{%0,%1,%2,%3}, {%4,%5,%6,%7}, {%8,%9}, {%0,%1,%2,%3};" \
                 : "+f"((c)[0]), "+f"((c)[1]), "+f"((c)[2]), "+f"((c)[3]) \
                 : "r"((a)[0]), "r"((a)[1]), "r"((a)[2]), "r"((a)[3]), \
                   "r"(b0), "r"(b1))

#define CP_ASYNC16(dst, src) \
    asm volatile("cp.async.cg.shared.global [%0], [%1], 16;" :: "r"(dst), "l"(src))
#define CP_COMMIT() asm volatile("cp.async.commit_group;" ::: "memory")

// ---------------------------------------------------------------------------
// Kernel A: thresholds + counter zero + fp16 hi/lo conversion of both inputs.
// ---------------------------------------------------------------------------
__global__ void prep_kernel(const float* __restrict__ x1,
                            const float* __restrict__ x2) {
    int warp = (blockIdx.x * blockDim.x + threadIdx.x) >> 5;
    int lane = threadIdx.x & 31;
    if (warp >= ROWS) return;
    float4 a = *(const float4*)(x1 + warp * KDIM + lane * 4);
    float4 b = *(const float4*)(x2 + warp * KDIM + lane * 4);

    int base = warp * KDIM + lane * 4;
    {
        __half h0 = __float2half_rn(a.x), h1 = __float2half_rn(a.y);
        __half h2 = __float2half_rn(a.z), h3 = __float2half_rn(a.w);
        half2 H0 = __halves2half2(h0, h1), H1 = __halves2half2(h2, h3);
        *(uint2*)(g_x1h + base) = make_uint2(*(unsigned*)&H0, *(unsigned*)&H1);
        __half l0 = __float2half_rn(a.x - __half2float(h0));
        __half l1 = __float2half_rn(a.y - __half2float(h1));
        __half l2 = __float2half_rn(a.z - __half2float(h2));
        __half l3 = __float2half_rn(a.w - __half2float(h3));
        half2 L0 = __halves2half2(l0, l1), L1 = __halves2half2(l2, l3);
        *(uint2*)(g_x1l + base) = make_uint2(*(unsigned*)&L0, *(unsigned*)&L1);
    }
    {
        __half h0 = __float2half_rn(b.x), h1 = __float2half_rn(b.y);
        __half h2 = __float2half_rn(b.z), h3 = __float2half_rn(b.w);
        half2 H0 = __halves2half2(h0, h1), H1 = __halves2half2(h2, h3);
        *(uint2*)(g_x2h + base) = make_uint2(*(unsigned*)&H0, *(unsigned*)&H1);
        __half l0 = __float2half_rn(b.x - __half2float(h0));
        __half l1 = __float2half_rn(b.y - __half2float(h1));
        __half l2 = __float2half_rn(b.z - __half2float(h2));
        __half l3 = __float2half_rn(b.w - __half2float(h3));
        half2 L0 = __halves2half2(l0, l1), L1 = __halves2half2(l2, l3);
        *(uint2*)(g_x2l + base) = make_uint2(*(unsigned*)&L0, *(unsigned*)&L1);
    }

    float s1 = a.x * a.x + a.y * a.y + a.z * a.z + a.w * a.w;
    float s2 = b.x * b.x + b.y * b.y + b.z * b.z + b.w * b.w;
    float d  = a.x * b.x + a.y * b.y + a.z * b.z + a.w * b.w;
    #pragma unroll
    for (int o = 16; o > 0; o >>= 1) {
        s1 += __shfl_down_sync(0xffffffffu, s1, o);
        s2 += __shfl_down_sync(0xffffffffu, s2, o);
        d  += __shfl_down_sync(0xffffffffu, d,  o);
    }
    if (lane == 0) {
        float n2 = sqrtf(s2);
        g_n1[warp]  = sqrtf(s1);
        g_n2[warp]  = n2;
        g_r[warp]   = d / n2;
        g_cnt[warp] = 0;
    }
}

// ---------------------------------------------------------------------------
// Kernel B: hh-only counting GEMM + queued borderline fixup from SMEM.
// Tile BM=128 x BN=256, 512 threads, K=128 resident in 4 slabs of 48 KB:
//   [0,8K)=A_hi  [8K,16K)=A_lo  [16K,32K)=B_hi  [32K,48K)=B_lo
// Rows 64B, 16B-slot swizzle slot ^= (row>>1)&3.
// ---------------------------------------------------------------------------
#define CHUNK_SZ   49152
#define SMEM_TOTAL (4 * CHUNK_SZ)      // 192 KB dynamic

__device__ __forceinline__ void load_chunk(uint32_t bufb, int i0, int j0,
                                           int kc, int tid) {
    const int s  = tid & 3;
    const int rh = tid >> 2;           // 0..127
    const int swsh = ((s ^ ((rh >> 1) & 3)) << 4);
    CP_ASYNC16(bufb +         rh * 64 + swsh, g_x1h + (i0 + rh) * KDIM + kc + s * 8);
    CP_ASYNC16(bufb +  8192 + rh * 64 + swsh, g_x1l + (i0 + rh) * KDIM + kc + s * 8);
    const int r2 = rh + 128;
    const int swsh2 = ((s ^ ((r2 >> 1) & 3)) << 4);
    CP_ASYNC16(bufb + 16384 + rh * 64 + swsh,  g_x2h + (j0 + rh) * KDIM + kc + s * 8);
    CP_ASYNC16(bufb + 16384 + r2 * 64 + swsh2, g_x2h + (j0 + r2) * KDIM + kc + s * 8);
    CP_ASYNC16(bufb + 32768 + rh * 64 + swsh,  g_x2l + (j0 + rh) * KDIM + kc + s * 8);
    CP_ASYNC16(bufb + 32768 + r2 * 64 + swsh2, g_x2l + (j0 + r2) * KDIM + kc + s * 8);
}

__device__ __forceinline__ void compute_chunk(uint32_t bufb, int wm, int wn,
                                              int l, float acc[4][4][4]) {
    const int lg = l >> 3, lr = l & 7;
    #pragma unroll
    for (int t = 0; t < 2; t++) {               // two k16 steps per chunk
        uint32_t ah[4][4];
        #pragma unroll
        for (int tm = 0; tm < 4; tm++) {
            const int row  = wm * 64 + tm * 16 + ((lg & 1) << 3) + lr;
            const int slot = 2 * t + (lg >> 1);
            const uint32_t off = row * 64 + ((slot ^ ((row >> 1) & 3)) << 4);
            LDSM_X4(ah[tm][0], ah[tm][1], ah[tm][2], ah[tm][3], bufb + off);
        }
        #pragma unroll
        for (int p = 0; p < 2; p++) {
            const int row  = wn * 32 + p * 16 + ((lg >> 1) << 3) + lr;
            const int slot = 2 * t + (lg & 1);
            const uint32_t off = row * 64 + ((slot ^ ((row >> 1) & 3)) << 4);
            uint32_t bh[4];
            LDSM_X4(bh[0], bh[1], bh[2], bh[3], bufb + 16384 + off);
            #pragma unroll
            for (int tm = 0; tm < 4; tm++) {
                MMA_16816(acc[tm][2 * p],     ah[tm], bh[0], bh[1]);
                MMA_16816(acc[tm][2 * p + 1], ah[tm], bh[2], bh[3]);
            }
        }
    }
}

// correction for 8 k-values: al*bh + ah*bl + al*bl  (fp32)
__device__ __forceinline__ float corr8(uint4 AH, uint4 AL, uint4 BH, uint4 BL) {
    float c = 0.f;
    const unsigned* ah = &AH.x; const unsigned* al = &AL.x;
    const unsigned* bh = &BH.x; const unsigned* bl = &BL.x;
    #pragma unroll
    for (int w = 0; w < 4; w++) {
        float2 fah = __half22float2(*(const half2*)&ah[w]);
        float2 fal = __half22float2(*(const half2*)&al[w]);
        float2 fbh = __half22float2(*(const half2*)&bh[w]);
        float2 fbl = __half22float2(*(const half2*)&bl[w]);
        c += fal.x * (fbh.x + fbl.x) + fah.x * fbl.x;
        c += fal.y * (fbh.y + fbl.y) + fah.y * fbl.y;
    }
    return c;
}

__device__ __forceinline__ float exact_dot_lane(const float* __restrict__ x1,
                                                const float* __restrict__ x2,
                                                int i, int j) {
    const float4* pa = (const float4*)(x1 + i * KDIM);
    const float4* pb = (const float4*)(x2 + j * KDIM);
    float s = 0.f;
    #pragma unroll 8
    for (int k = 0; k < 32; k++) {
        float4 a = pa[k], b = pb[k];
        s += a.x * b.x; s += a.y * b.y; s += a.z * b.z; s += a.w * b.w;
    }
    return s;
}

__global__ __launch_bounds__(512, 1)
void count_kernel(const float* __restrict__ x1, const float* __restrict__ x2) {
    extern __shared__ char smem[];
    __shared__ unsigned q_ij[QCAP];
    __shared__ float    q_m[QCAP];
    __shared__ int      q_n;

    const uint32_t sb = smem_u32(smem);
    const int tid = threadIdx.x;
    const int l   = tid & 31;
    const int wid = tid >> 5;
    const int wm  = wid >> 3;        // 0..1
    const int wn  = wid & 7;         // 0..7
    const int i0  = blockIdx.y * 128;
    const int j0  = blockIdx.x * 256;

    if (tid == 0) q_n = 0;

    #pragma unroll
    for (int c = 0; c < 4; c++) {
        load_chunk(sb + c * CHUNK_SZ, i0, j0, c * 32, tid);
        CP_COMMIT();
    }

    float acc[4][4][4];
    #pragma unroll
    for (int a = 0; a < 4; a++)
        #pragma unroll
        for (int b = 0; b < 4; b++)
            #pragma unroll
            for (int c = 0; c < 4; c++) acc[a][b][c] = 0.f;

    #pragma unroll
    for (int c = 0; c < 4; c++) {
        switch (c) {
            case 0: asm volatile("cp.async.wait_group 3;" ::: "memory"); break;
            case 1: asm volatile("cp.async.wait_group 2;" ::: "memory"); break;
            case 2: asm volatile("cp.async.wait_group 1;" ::: "memory"); break;
            default: asm volatile("cp.async.wait_group 0;" ::: "memory"); break;
        }
        __syncthreads();
        compute_chunk(sb + c * CHUNK_SZ, wm, wn, l, acc);
    }

    // Epilogue: certain decisions counted now; borderline queued.
    float na[4], nb[4];
    #pragma unroll
    for (int tn = 0; tn < 4; tn++) {
        const int jb = j0 + wn * 32 + tn * 8 + ((l & 3) << 1);
        na[tn] = __ldg(&g_n2[jb]);
        nb[tn] = __ldg(&g_n2[jb + 1]);
    }

    #pragma unroll
    for (int tm = 0; tm < 4; tm++) {
        const int r0 = i0 + wm * 64 + tm * 16 + (l >> 2);
        const int r1 = r0 + 8;
        const float th0 = __ldg(&g_r[r0]);
        const float th1 = __ldg(&g_r[r1]);
        const float e0  = EPS * __ldg(&g_n1[r0]);
        const float e1  = EPS * __ldg(&g_n1[r1]);
        int c0 = 0, c1 = 0;
        #pragma unroll
        for (int tn = 0; tn < 4; tn++) {
            const int jb = j0 + wn * 32 + tn * 8 + ((l & 3) << 1);
            #pragma unroll
            for (int q = 0; q < 4; q++) {
                const int   ri  = (q < 2) ? r0 : r1;
                const float th  = (q < 2) ? th0 : th1;
                const float er  = (q < 2) ? e0 : e1;
                const int   jj  = jb + (q & 1);
                const float nv  = (q & 1) ? nb[tn] : na[tn];
                const float rhs = th * nv;
                const float m   = acc[tm][tn][q] - rhs;
                const float eps = er * nv;
                int hit = (m > eps) ? 1 : 0;
                if (m <= eps && m >= -eps) {
                    int slot = atomicAdd(&q_n, 1);
                    if (slot < QCAP) {
                        q_ij[slot] = (unsigned)(((ri - i0) << 8) | (jj - j0));
                        q_m[slot]  = m;
                    } else {  // overflow fallback (statistically never)
                        float s = exact_dot_lane(x1, x2, ri, jj);
                        hit = (s > rhs && jj != ri) ? 1 : 0;
                    }
                }
                if (q < 2) c0 += hit; else c1 += hit;
            }
        }
        c0 += __shfl_xor_sync(0xffffffffu, c0, 1);
        c0 += __shfl_xor_sync(0xffffffffu, c0, 2);
        c1 += __shfl_xor_sync(0xffffffffu, c1, 1);
        c1 += __shfl_xor_sync(0xffffffffu, c1, 2);
        if ((l & 3) == 0) {
            atomicAdd(&g_cnt[r0], c0);
            atomicAdd(&g_cnt[r1], c1);
        }
    }

    // Drain: one queue entry per lane; correction computed from SMEM.
    __syncthreads();
    const int qn = min(q_n, QCAP);
    for (int e = tid; e < qn; e += 512) {
        const unsigned ij = q_ij[e];
        const int li = (int)(ij >> 8), lj = (int)(ij & 255u);
        const int gi = i0 + li, gj = j0 + lj;
        const uint32_t swA = ((li >> 1) & 3);
        const uint32_t swB = ((lj >> 1) & 3);
        float corr = 0.f;
        #pragma unroll
        for (int c = 0; c < 4; c++) {
            const char* base = smem + c * CHUNK_SZ;
            #pragma unroll
            for (int s = 0; s < 4; s++) {
                const uint32_t oa = li * 64 + (((uint32_t)s ^ swA) << 4);
                const uint32_t ob = lj * 64 + (((uint32_t)s ^ swB) << 4);
                uint4 AH = *(const uint4*)(base + oa);
                uint4 AL = *(const uint4*)(base + 8192 + oa);
                uint4 BH = *(const uint4*)(base + 16384 + ob);
                uint4 BL = *(const uint4*)(base + 32768 + ob);
                corr += corr8(AH, AL, BH, BL);
            }
        }
        const float n1v = __ldg(&g_n1[gi]);
        const float n2v = __ldg(&g_n2[gj]);
        const float tot = q_m[e] + corr;
        int hit;
        if (fabsf(tot) > EPS2 * n1v * n2v) {
            hit = (tot > 0.f && gj != gi) ? 1 : 0;
        } else {          // ultra-borderline (~6 per CTA): exact fp32 from gmem
            const float rhs = __ldg(&g_r[gi]) * n2v;
            const float s = exact_dot_lane(x1, x2, gi, gj);
            hit = (s > rhs && gj != gi) ? 1 : 0;
        }
        if (hit) atomicAdd(&g_cnt[gi], 1);
    }
}

// ---------------------------------------------------------------------------
// Kernel C: mean of (count < NPER)
// ---------------------------------------------------------------------------
__global__ void finalize_kernel(float* __restrict__ out) {
    __shared__ int sh[256];
    int t = threadIdx.x;
    int c = 0;
    for (int i = t; i < ROWS; i += 256) c += (g_cnt[i] < NPER) ? 1 : 0;
    sh[t] = c;
    __syncthreads();
    #pragma unroll
    for (int s = 128; s > 0; s >>= 1) {
        if (t < s) sh[t] += sh[t + s];
        __syncthreads();
    }
    if (t == 0) out[0] = (float)sh[0] / (float)ROWS;
}

// ---------------------------------------------------------------------------
extern "C" void kernel_launch(void* const* d_in, const int* in_sizes, int n_in,
                              void* d_out, int out_size) {
    const float* x1 = (const float*)d_in[0];
    const float* x2 = (const float*)d_in[1];
    float* out = (float*)d_out;
    (void)in_sizes; (void)n_in; (void)out_size;

    cudaFuncSetAttribute(count_kernel,
                         cudaFuncAttributeMaxDynamicSharedMemorySize, SMEM_TOTAL);

    prep_kernel<<<ROWS / 8, 256>>>(x1, x2);
    count_kernel<<<dim3(32, 64), 512, SMEM_TOTAL>>>(x1, x2);
    finalize_kernel<<<1, 256>>>(out);
}

// round 11
// speedup vs baseline: 1.9212x; 1.9212x over previous
#include <cuda_runtime.h>
#include <cuda_fp16.h>
#include <cstdint>

#define ROWS 8192
#define KDIM 128
#define NPER 82        // int(8192 * 1 / 100) + 1

// Scratch (device globals: no allocation allowed)
__device__ float  g_r[ROWS];            // dot(x1_i, x2_i) / ||x2_i||
__device__ float  g_n2[ROWS];           // ||x2_j||
__device__ int    g_cnt[ROWS];          // per-row count of strictly-greater sims
__device__ __half g_x1h[ROWS * KDIM];   // fp16 hi/lo split of inputs
__device__ __half g_x1l[ROWS * KDIM];
__device__ __half g_x2h[ROWS * KDIM];
__device__ __half g_x2l[ROWS * KDIM];

__device__ __forceinline__ uint32_t smem_u32(const void* p) {
    uint32_t a;
    asm("{ .reg .u64 t; cvta.to.shared.u64 t, %1; cvt.u32.u64 %0, t; }"
        : "=r"(a) : "l"(p));
    return a;
}

#define LDSM_X4(r0, r1, r2, r3, addr) \
    asm volatile("ldmatrix.sync.aligned.m8n8.x4.shared.b16 {%0,%1,%2,%3}, [%4];" \
                 : "=r"(r0), "=r"(r1), "=r"(r2), "=r"(r3) : "r"(addr))

#define MMA_16816(c, a, b0, b1) \
    asm volatile("mma.sync.aligned.m16n8k16.row.col.f32.f16.f16.f32 " \
                 "{%0,%1,%2,%3}, {%4,%5,%6,%7}, {%8,%9}, {%0,%1,%2,%3};" \
                 : "+f"((c)[0]), "+f"((c)[1]), "+f"((c)[2]), "+f"((c)[3]) \
                 : "r"((a)[0]), "r"((a)[1]), "r"((a)[2]), "r"((a)[3]), \
                   "r"(b0), "r"(b1))

#define CP_ASYNC16(dst, src) \
    asm volatile("cp.async.cg.shared.global [%0], [%1], 16;" :: "r"(dst), "l"(src))
#define CP_COMMIT() asm volatile("cp.async.commit_group;" ::: "memory")

// ---------------------------------------------------------------------------
// Kernel A: thresholds + counter zero + fp16 hi/lo conversion of both inputs.
// ---------------------------------------------------------------------------
__global__ void prep_kernel(const float* __restrict__ x1,
                            const float* __restrict__ x2) {
    int warp = (blockIdx.x * blockDim.x + threadIdx.x) >> 5;
    int lane = threadIdx.x & 31;
    if (warp >= ROWS) return;
    float4 a = *(const float4*)(x1 + warp * KDIM + lane * 4);
    float4 b = *(const float4*)(x2 + warp * KDIM + lane * 4);

    int base = warp * KDIM + lane * 4;
    {
        __half h0 = __float2half_rn(a.x), h1 = __float2half_rn(a.y);
        __half h2 = __float2half_rn(a.z), h3 = __float2half_rn(a.w);
        half2 H0 = __halves2half2(h0, h1), H1 = __halves2half2(h2, h3);
        *(uint2*)(g_x1h + base) = make_uint2(*(unsigned*)&H0, *(unsigned*)&H1);
        __half l0 = __float2half_rn(a.x - __half2float(h0));
        __half l1 = __float2half_rn(a.y - __half2float(h1));
        __half l2 = __float2half_rn(a.z - __half2float(h2));
        __half l3 = __float2half_rn(a.w - __half2float(h3));
        half2 L0 = __halves2half2(l0, l1), L1 = __halves2half2(l2, l3);
        *(uint2*)(g_x1l + base) = make_uint2(*(unsigned*)&L0, *(unsigned*)&L1);
    }
    {
        __half h0 = __float2half_rn(b.x), h1 = __float2half_rn(b.y);
        __half h2 = __float2half_rn(b.z), h3 = __float2half_rn(b.w);
        half2 H0 = __halves2half2(h0, h1), H1 = __halves2half2(h2, h3);
        *(uint2*)(g_x2h + base) = make_uint2(*(unsigned*)&H0, *(unsigned*)&H1);
        __half l0 = __float2half_rn(b.x - __half2float(h0));
        __half l1 = __float2half_rn(b.y - __half2float(h1));
        __half l2 = __float2half_rn(b.z - __half2float(h2));
        __half l3 = __float2half_rn(b.w - __half2float(h3));
        half2 L0 = __halves2half2(l0, l1), L1 = __halves2half2(l2, l3);
        *(uint2*)(g_x2l + base) = make_uint2(*(unsigned*)&L0, *(unsigned*)&L1);
    }

    float s2 = b.x * b.x + b.y * b.y + b.z * b.z + b.w * b.w;
    float d  = a.x * b.x + a.y * b.y + a.z * b.z + a.w * b.w;
    #pragma unroll
    for (int o = 16; o > 0; o >>= 1) {
        s2 += __shfl_down_sync(0xffffffffu, s2, o);
        d  += __shfl_down_sync(0xffffffffu, d,  o);
    }
    if (lane == 0) {
        float n2 = sqrtf(s2);
        g_n2[warp]  = n2;
        g_r[warp]   = d / n2;
        g_cnt[warp] = 0;
    }
}

// ---------------------------------------------------------------------------
// Kernel B: counting GEMM via mma.sync m16n8k16 fp16, 3-term hi/lo split.
// Tile BM=128 x BN=256, 512 threads (16 warps, 2x8), warp tile 64x32.
// Whole K=128 resident: 4 chunk-slabs of 48 KB, all cp.async up front.
// MMA issue order is PASS-MAJOR within each (t,p) block: 8 independent
// accumulators between successive uses of the same acc (hides HMMA latency;
// the previous tile-major order chained hh->hl->lh on one acc back-to-back).
// ---------------------------------------------------------------------------
#define CHUNK_SZ   49152
#define SMEM_TOTAL (4 * CHUNK_SZ)      // 192 KB

__device__ __forceinline__ void load_chunk(uint32_t bufb, int i0, int j0,
                                           int kc, int tid) {
    const int s  = tid & 3;            // 16B slot within 64B chunk-row
    const int rh = tid >> 2;           // 0..127
    const int swsh = ((s ^ ((rh >> 1) & 3)) << 4);
    CP_ASYNC16(bufb +         rh * 64 + swsh, g_x1h + (i0 + rh) * KDIM + kc + s * 8);
    CP_ASYNC16(bufb +  8192 + rh * 64 + swsh, g_x1l + (i0 + rh) * KDIM + kc + s * 8);
    const int r2 = rh + 128;
    const int swsh2 = ((s ^ ((r2 >> 1) & 3)) << 4);
    CP_ASYNC16(bufb + 16384 + rh * 64 + swsh,  g_x2h + (j0 + rh) * KDIM + kc + s * 8);
    CP_ASYNC16(bufb + 16384 + r2 * 64 + swsh2, g_x2h + (j0 + r2) * KDIM + kc + s * 8);
    CP_ASYNC16(bufb + 32768 + rh * 64 + swsh,  g_x2l + (j0 + rh) * KDIM + kc + s * 8);
    CP_ASYNC16(bufb + 32768 + r2 * 64 + swsh2, g_x2l + (j0 + r2) * KDIM + kc + s * 8);
}

__device__ __forceinline__ void compute_chunk(uint32_t bufb, int wm, int wn,
                                              int l, float acc[4][4][4]) {
    const int lg = l >> 3, lr = l & 7;
    #pragma unroll
    for (int t = 0; t < 2; t++) {               // two k16 steps per chunk
        uint32_t ah[4][4], al[4][4];
        #pragma unroll
        for (int tm = 0; tm < 4; tm++) {
            const int row  = wm * 64 + tm * 16 + ((lg & 1) << 3) + lr;
            const int slot = 2 * t + (lg >> 1);
            const uint32_t off = row * 64 + ((slot ^ ((row >> 1) & 3)) << 4);
            LDSM_X4(ah[tm][0], ah[tm][1], ah[tm][2], ah[tm][3], bufb + off);
            LDSM_X4(al[tm][0], al[tm][1], al[tm][2], al[tm][3], bufb + 8192 + off);
        }
        #pragma unroll
        for (int p = 0; p < 2; p++) {           // n-tile pairs (2p, 2p+1)
            const int row  = wn * 32 + p * 16 + ((lg >> 1) << 3) + lr;
            const int slot = 2 * t + (lg & 1);
            const uint32_t off = row * 64 + ((slot ^ ((row >> 1) & 3)) << 4);
            uint32_t bh[4], bl[4];
            LDSM_X4(bh[0], bh[1], bh[2], bh[3], bufb + 16384 + off);
            LDSM_X4(bl[0], bl[1], bl[2], bl[3], bufb + 32768 + off);
            // pass hh: 8 independent accumulators
            #pragma unroll
            for (int tm = 0; tm < 4; tm++) {
                MMA_16816(acc[tm][2 * p],     ah[tm], bh[0], bh[1]);
                MMA_16816(acc[tm][2 * p + 1], ah[tm], bh[2], bh[3]);
            }
            // pass hl
            #pragma unroll
            for (int tm = 0; tm < 4; tm++) {
                MMA_16816(acc[tm][2 * p],     ah[tm], bl[0], bl[1]);
                MMA_16816(acc[tm][2 * p + 1], ah[tm], bl[2], bl[3]);
            }
            // pass lh
            #pragma unroll
            for (int tm = 0; tm < 4; tm++) {
                MMA_16816(acc[tm][2 * p],     al[tm], bh[0], bh[1]);
                MMA_16816(acc[tm][2 * p + 1], al[tm], bh[2], bh[3]);
            }
        }
    }
}

__global__ __launch_bounds__(512, 1)
void count_kernel() {
    extern __shared__ char smem[];
    const uint32_t sb = smem_u32(smem);
    const int tid = threadIdx.x;
    const int l   = tid & 31;
    const int wid = tid >> 5;        // 0..15
    const int wm  = wid >> 3;        // 0..1  (64-row m slab)
    const int wn  = wid & 7;         // 0..7  (32-col n slab)
    const int i0  = blockIdx.y * 128;
    const int j0  = blockIdx.x * 256;

    #pragma unroll
    for (int c = 0; c < 4; c++) {
        load_chunk(sb + c * CHUNK_SZ, i0, j0, c * 32, tid);
        CP_COMMIT();
    }

    float acc[4][4][4];
    #pragma unroll
    for (int a = 0; a < 4; a++)
        #pragma unroll
        for (int b = 0; b < 4; b++)
            #pragma unroll
            for (int c = 0; c < 4; c++) acc[a][b][c] = 0.f;

    #pragma unroll
    for (int c = 0; c < 4; c++) {
        switch (c) {
            case 0: asm volatile("cp.async.wait_group 3;" ::: "memory"); break;
            case 1: asm volatile("cp.async.wait_group 2;" ::: "memory"); break;
            case 2: asm volatile("cp.async.wait_group 1;" ::: "memory"); break;
            default: asm volatile("cp.async.wait_group 0;" ::: "memory"); break;
        }
        __syncthreads();
        compute_chunk(sb + c * CHUNK_SZ, wm, wn, l, acc);
    }

    // Epilogue: compare dot > r_i * n2_j, exclude diagonal, count per row.
    float na[4], nb[4];
    #pragma unroll
    for (int tn = 0; tn < 4; tn++) {
        const int jb = j0 + wn * 32 + tn * 8 + ((l & 3) << 1);
        na[tn] = __ldg(&g_n2[jb]);
        nb[tn] = __ldg(&g_n2[jb + 1]);
    }
    #pragma unroll
    for (int tm = 0; tm < 4; tm++) {
        const int r0 = i0 + wm * 64 + tm * 16 + (l >> 2);
        const int r1 = r0 + 8;
        const float th0 = __ldg(&g_r[r0]);
        const float th1 = __ldg(&g_r[r1]);
        int c0 = 0, c1 = 0;
        #pragma unroll
        for (int tn = 0; tn < 4; tn++) {
            const int jb = j0 + wn * 32 + tn * 8 + ((l & 3) << 1);
            c0 += (acc[tm][tn][0] > th0 * na[tn] && jb     != r0) ? 1 : 0;
            c0 += (acc[tm][tn][1] > th0 * nb[tn] && jb + 1 != r0) ? 1 : 0;
            c1 += (acc[tm][tn][2] > th1 * na[tn] && jb     != r1) ? 1 : 0;
            c1 += (acc[tm][tn][3] > th1 * nb[tn] && jb + 1 != r1) ? 1 : 0;
        }
        c0 += __shfl_xor_sync(0xffffffffu, c0, 1);
        c0 += __shfl_xor_sync(0xffffffffu, c0, 2);
        c1 += __shfl_xor_sync(0xffffffffu, c1, 1);
        c1 += __shfl_xor_sync(0xffffffffu, c1, 2);
        if ((l & 3) == 0) {
            atomicAdd(&g_cnt[r0], c0);
            atomicAdd(&g_cnt[r1], c1);
        }
    }
}

// ---------------------------------------------------------------------------
// Kernel C: mean of (count < NPER)
// ---------------------------------------------------------------------------
__global__ void finalize_kernel(float* __restrict__ out) {
    __shared__ int sh[256];
    int t = threadIdx.x;
    int c = 0;
    for (int i = t; i < ROWS; i += 256) c += (g_cnt[i] < NPER) ? 1 : 0;
    sh[t] = c;
    __syncthreads();
    #pragma unroll
    for (int s = 128; s > 0; s >>= 1) {
        if (t < s) sh[t] += sh[t + s];
        __syncthreads();
    }
    if (t == 0) out[0] = (float)sh[0] / (float)ROWS;
}

// ---------------------------------------------------------------------------
extern "C" void kernel_launch(void* const* d_in, const int* in_sizes, int n_in,
                              void* d_out, int out_size) {
    const float* x1 = (const float*)d_in[0];
    const float* x2 = (const float*)d_in[1];
    float* out = (float*)d_out;
    (void)in_sizes; (void)n_in; (void)out_size;

    cudaFuncSetAttribute(count_kernel,
                         cudaFuncAttributeMaxDynamicSharedMemorySize, SMEM_TOTAL);

    prep_kernel<<<ROWS / 8, 256>>>(x1, x2);
    count_kernel<<<dim3(32, 64), 512, SMEM_TOTAL>>>();
    finalize_kernel<<<1, 256>>>(out);
}

// round 12
// speedup vs baseline: 3.0461x; 1.5855x over previous
#include <cuda_runtime.h>
#include <cuda_fp16.h>
#include <cstdint>

#define ROWS 8192
#define KDIM 128
#define NPER 82          // int(8192 * 1 / 100) + 1
#define EPS  1.25e-3f    // certified |dot_hh - dot| bound coeff (x ||a||*||b||)

// Scratch (device globals: no allocation allowed)
__device__ float  g_r[ROWS];            // dot(x1_i, x2_i) / ||x2_i||
__device__ float  g_n1[ROWS];           // ||x1_i||
__device__ float  g_n2[ROWS];           // ||x2_j||
__device__ int    g_cb[ROWS];           // packed (cert<<16 | bord)
__device__ int    g_cnt[ROWS];          // final per-row count (or 0 / NPER marker)
__device__ int    g_flag[ROWS];         // flagged row list
__device__ int    g_nflag;              // number of flagged rows
__device__ __half g_x1h[ROWS * KDIM];   // fp16 rn of inputs
__device__ __half g_x2h[ROWS * KDIM];

__device__ __forceinline__ uint32_t smem_u32(const void* p) {
    uint32_t a;
    asm("{ .reg .u64 t; cvta.to.shared.u64 t, %1; cvt.u32.u64 %0, t; }"
        : "=r"(a) : "l"(p));
    return a;
}

#define LDSM_X4(r0, r1, r2, r3, addr) \
    asm volatile("ldmatrix.sync.aligned.m8n8.x4.shared.b16 {%0,%1,%2,%3}, [%4];" \
                 : "=r"(r0), "=r"(r1), "=r"(r2), "=r"(r3) : "r"(addr))

#define MMA_16816(c, a, b0, b1) \
    asm volatile("mma.sync.aligned.m16n8k16.row.col.f32.f16.f16.f32 " \
                 "{%0,%1,%2,%3}, {%4,%5,%6,%7}, {%8,%9}, {%0,%1,%2,%3};" \
                 : "+f"((c)[0]), "+f"((c)[1]), "+f"((c)[2]), "+f"((c)[3]) \
                 : "r"((a)[0]), "r"((a)[1]), "r"((a)[2]), "r"((a)[3]), \
                   "r"(b0), "r"(b1))

#define CP_ASYNC16(dst, src) \
    asm volatile("cp.async.cg.shared.global [%0], [%1], 16;" :: "r"(dst), "l"(src))
#define CP_COMMIT() asm volatile("cp.async.commit_group;" ::: "memory")

// ---------------------------------------------------------------------------
// Kernel A: thresholds + zero counters + fp16 conversion of both inputs.
// ---------------------------------------------------------------------------
__global__ void prep_kernel(const float* __restrict__ x1,
                            const float* __restrict__ x2) {
    int warp = (blockIdx.x * blockDim.x + threadIdx.x) >> 5;
    int lane = threadIdx.x & 31;
    if (warp >= ROWS) return;
    float4 a = *(const float4*)(x1 + warp * KDIM + lane * 4);
    float4 b = *(const float4*)(x2 + warp * KDIM + lane * 4);

    int base = warp * KDIM + lane * 4;
    {
        __half h0 = __float2half_rn(a.x), h1 = __float2half_rn(a.y);
        __half h2 = __float2half_rn(a.z), h3 = __float2half_rn(a.w);
        half2 H0 = __halves2half2(h0, h1), H1 = __halves2half2(h2, h3);
        *(uint2*)(g_x1h + base) = make_uint2(*(unsigned*)&H0, *(unsigned*)&H1);
    }
    {
        __half h0 = __float2half_rn(b.x), h1 = __float2half_rn(b.y);
        __half h2 = __float2half_rn(b.z), h3 = __float2half_rn(b.w);
        half2 H0 = __halves2half2(h0, h1), H1 = __halves2half2(h2, h3);
        *(uint2*)(g_x2h + base) = make_uint2(*(unsigned*)&H0, *(unsigned*)&H1);
    }

    float s1 = a.x * a.x + a.y * a.y + a.z * a.z + a.w * a.w;
    float s2 = b.x * b.x + b.y * b.y + b.z * b.z + b.w * b.w;
    float d  = a.x * b.x + a.y * b.y + a.z * b.z + a.w * b.w;
    #pragma unroll
    for (int o = 16; o > 0; o >>= 1) {
        s1 += __shfl_down_sync(0xffffffffu, s1, o);
        s2 += __shfl_down_sync(0xffffffffu, s2, o);
        d  += __shfl_down_sync(0xffffffffu, d,  o);
    }
    if (lane == 0) {
        float n2 = sqrtf(s2);
        g_n1[warp] = sqrtf(s1);
        g_n2[warp] = n2;
        g_r[warp]  = d / n2;
        g_cb[warp] = 0;
        if (warp == 0) g_nflag = 0;
    }
}

// ---------------------------------------------------------------------------
// Kernel B: hh-only counting GEMM. Per row accumulates packed
// (certain-greater count << 16) | (borderline count).
// Tile BM=128 x BN=256, 512 threads (16 warps, 2x8), warp tile 64x32.
// K=128 fully resident: 4 slabs of 24 KB (A_hi 8K, B_hi 16K), swizzled rows.
// ---------------------------------------------------------------------------
#define CHUNK_SZ   24576
#define SMEM_TOTAL (4 * CHUNK_SZ)      // 96 KB

__device__ __forceinline__ void load_chunk(uint32_t bufb, int i0, int j0,
                                           int kc, int tid) {
    const int s  = tid & 3;
    const int rh = tid >> 2;           // 0..127
    const int swsh = ((s ^ ((rh >> 1) & 3)) << 4);
    CP_ASYNC16(bufb +        rh * 64 + swsh, g_x1h + (i0 + rh) * KDIM + kc + s * 8);
    CP_ASYNC16(bufb + 8192 + rh * 64 + swsh, g_x2h + (j0 + rh) * KDIM + kc + s * 8);
    const int r2 = rh + 128;
    const int swsh2 = ((s ^ ((r2 >> 1) & 3)) << 4);
    CP_ASYNC16(bufb + 8192 + r2 * 64 + swsh2, g_x2h + (j0 + r2) * KDIM + kc + s * 8);
}

__device__ __forceinline__ void compute_chunk(uint32_t bufb, int wm, int wn,
                                              int l, float acc[4][4][4]) {
    const int lg = l >> 3, lr = l & 7;
    #pragma unroll
    for (int t = 0; t < 2; t++) {
        uint32_t ah[4][4];
        #pragma unroll
        for (int tm = 0; tm < 4; tm++) {
            const int row  = wm * 64 + tm * 16 + ((lg & 1) << 3) + lr;
            const int slot = 2 * t + (lg >> 1);
            const uint32_t off = row * 64 + ((slot ^ ((row >> 1) & 3)) << 4);
            LDSM_X4(ah[tm][0], ah[tm][1], ah[tm][2], ah[tm][3], bufb + off);
        }
        #pragma unroll
        for (int p = 0; p < 2; p++) {
            const int row  = wn * 32 + p * 16 + ((lg >> 1) << 3) + lr;
            const int slot = 2 * t + (lg & 1);
            const uint32_t off = row * 64 + ((slot ^ ((row >> 1) & 3)) << 4);
            uint32_t bh[4];
            LDSM_X4(bh[0], bh[1], bh[2], bh[3], bufb + 8192 + off);
            #pragma unroll
            for (int tm = 0; tm < 4; tm++) {
                MMA_16816(acc[tm][2 * p],     ah[tm], bh[0], bh[1]);
                MMA_16816(acc[tm][2 * p + 1], ah[tm], bh[2], bh[3]);
            }
        }
    }
}

__global__ __launch_bounds__(512, 1)
void pass1_kernel() {
    extern __shared__ char smem[];
    const uint32_t sb = smem_u32(smem);
    const int tid = threadIdx.x;
    const int l   = tid & 31;
    const int wid = tid >> 5;
    const int wm  = wid >> 3;
    const int wn  = wid & 7;
    const int i0  = blockIdx.y * 128;
    const int j0  = blockIdx.x * 256;

    #pragma unroll
    for (int c = 0; c < 4; c++) {
        load_chunk(sb + c * CHUNK_SZ, i0, j0, c * 32, tid);
        CP_COMMIT();
    }

    float acc[4][4][4];
    #pragma unroll
    for (int a = 0; a < 4; a++)
        #pragma unroll
        for (int b = 0; b < 4; b++)
            #pragma unroll
            for (int c = 0; c < 4; c++) acc[a][b][c] = 0.f;

    #pragma unroll
    for (int c = 0; c < 4; c++) {
        switch (c) {
            case 0: asm volatile("cp.async.wait_group 3;" ::: "memory"); break;
            case 1: asm volatile("cp.async.wait_group 2;" ::: "memory"); break;
            case 2: asm volatile("cp.async.wait_group 1;" ::: "memory"); break;
            default: asm volatile("cp.async.wait_group 0;" ::: "memory"); break;
        }
        __syncthreads();
        compute_chunk(sb + c * CHUNK_SZ, wm, wn, l, acc);
    }

    // Epilogue: per row, cert = #(m > eps), bord = #(|m| <= eps).
    float na[4], nb[4];
    #pragma unroll
    for (int tn = 0; tn < 4; tn++) {
        const int jb = j0 + wn * 32 + tn * 8 + ((l & 3) << 1);
        na[tn] = __ldg(&g_n2[jb]);
        nb[tn] = __ldg(&g_n2[jb + 1]);
    }

    #pragma unroll
    for (int tm = 0; tm < 4; tm++) {
        const int r0 = i0 + wm * 64 + tm * 16 + (l >> 2);
        const int r1 = r0 + 8;
        const float th0 = __ldg(&g_r[r0]);
        const float th1 = __ldg(&g_r[r1]);
        const float e0  = EPS * __ldg(&g_n1[r0]);
        const float e1  = EPS * __ldg(&g_n1[r1]);
        int p0 = 0, p1 = 0;        // packed (cert<<8 | bord), per-thread <= 8 each
        #pragma unroll
        for (int tn = 0; tn < 4; tn++) {
            #pragma unroll
            for (int q = 0; q < 4; q++) {
                const float er  = (q < 2) ? e0 : e1;
                const float th  = (q < 2) ? th0 : th1;
                const float nv  = (q & 1) ? nb[tn] : na[tn];
                const float m   = acc[tm][tn][q] - th * nv;
                const float eps = er * nv;
                int add = (m > eps) ? 256 : ((m >= -eps) ? 1 : 0);
                if (q < 2) p0 += add; else p1 += add;
            }
        }
        p0 += __shfl_xor_sync(0xffffffffu, p0, 1);
        p0 += __shfl_xor_sync(0xffffffffu, p0, 2);
        p1 += __shfl_xor_sync(0xffffffffu, p1, 1);
        p1 += __shfl_xor_sync(0xffffffffu, p1, 2);
        if ((l & 3) == 0) {   // cert <= 32, bord <= 32 per packed field: no carry
            atomicAdd(&g_cb[r0], ((p0 >> 8) << 16) | (p0 & 0xff));
            atomicAdd(&g_cb[r1], ((p1 >> 8) << 16) | (p1 & 0xff));
        }
    }
}

// ---------------------------------------------------------------------------
// Kernel C: decide rows; flag undecidable ones.
// ---------------------------------------------------------------------------
__global__ void flag_kernel() {
    int i = blockIdx.x * blockDim.x + threadIdx.x;
    if (i >= ROWS) return;
    const int cb   = g_cb[i];
    const int cert = cb >> 16;
    const int bord = cb & 0xffff;
    if (cert >= NPER) {
        g_cnt[i] = NPER;               // certainly rank >= NPER: indicator 0
    } else if (cert + bord < NPER) {
        g_cnt[i] = 0;                  // certainly rank < NPER: indicator 1
    } else {
        g_cnt[i] = 0;                  // refined exactly below
        int slot = atomicAdd(&g_nflag, 1);
        g_flag[slot] = i;
    }
}

// ---------------------------------------------------------------------------
// Kernel D: exact fp32 refinement of flagged rows (~130-300 expected).
// Grid (64 j-slabs, 16 row-strides), 128 threads; thread owns one j in slab.
// ---------------------------------------------------------------------------
__global__ __launch_bounds__(128)
void refine_kernel(const float* __restrict__ x1, const float* __restrict__ x2) {
    __shared__ float x1row[KDIM];
    const int tid = threadIdx.x;
    const int j   = blockIdx.x * 128 + tid;
    const float n2j = g_n2[j];
    const int nf = g_nflag;

    for (int f = blockIdx.y; f < nf; f += 16) {
        const int row = g_flag[f];
        __syncthreads();
        x1row[tid] = x1[row * KDIM + tid];
        __syncthreads();
        // exact fp32 dot (same accumulation class validated in R1)
        const float4* pb = (const float4*)(x2 + j * KDIM);
        float s0 = 0.f, s1 = 0.f, s2 = 0.f, s3 = 0.f;
        #pragma unroll
        for (int k = 0; k < 32; k += 4) {
            float4 b0 = pb[k],     b1 = pb[k + 1];
            float4 b2 = pb[k + 2], b3 = pb[k + 3];
            const float* a0 = x1row + 4 * k;
            s0 += a0[0] * b0.x + a0[1] * b0.y + a0[2] * b0.z + a0[3] * b0.w;
            s1 += a0[4] * b1.x + a0[5] * b1.y + a0[6] * b1.z + a0[7] * b1.w;
            s2 += a0[8] * b2.x + a0[9] * b2.y + a0[10] * b2.z + a0[11] * b2.w;
            s3 += a0[12] * b3.x + a0[13] * b3.y + a0[14] * b3.z + a0[15] * b3.w;
        }
        const float s = (s0 + s1) + (s2 + s3);
        int c = (s > __ldg(&g_r[row]) * n2j && j != row) ? 1 : 0;
        #pragma unroll
        for (int o = 16; o > 0; o >>= 1) c += __shfl_xor_sync(0xffffffffu, c, o);
        if ((tid & 31) == 0 && c) atomicAdd(&g_cnt[row], c);
    }
}

// ---------------------------------------------------------------------------
// Kernel E: mean of (count < NPER)
// ---------------------------------------------------------------------------
__global__ void finalize_kernel(float* __restrict__ out) {
    __shared__ int sh[256];
    int t = threadIdx.x;
    int c = 0;
    for (int i = t; i < ROWS; i += 256) c += (g_cnt[i] < NPER) ? 1 : 0;
    sh[t] = c;
    __syncthreads();
    #pragma unroll
    for (int s = 128; s > 0; s >>= 1) {
        if (t < s) sh[t] += sh[t + s];
        __syncthreads();
    }
    if (t == 0) out[0] = (float)sh[0] / (float)ROWS;
}

// ---------------------------------------------------------------------------
extern "C" void kernel_launch(void* const* d_in, const int* in_sizes, int n_in,
                              void* d_out, int out_size) {
    const float* x1 = (const float*)d_in[0];
    const float* x2 = (const float*)d_in[1];
    float* out = (float*)d_out;
    (void)in_sizes; (void)n_in; (void)out_size;

    cudaFuncSetAttribute(pass1_kernel,
                         cudaFuncAttributeMaxDynamicSharedMemorySize, SMEM_TOTAL);

    prep_kernel<<<ROWS / 8, 256>>>(x1, x2);
    pass1_kernel<<<dim3(32, 64), 512, SMEM_TOTAL>>>();
    flag_kernel<<<ROWS / 256, 256>>>();
    refine_kernel<<<dim3(64, 16), 128>>>(x1, x2);
    finalize_kernel<<<1, 256>>>(out);
}

// round 13
// speedup vs baseline: 3.1899x; 1.0472x over previous
#include <cuda_runtime.h>
#include <cuda_fp16.h>
#include <cstdint>

#define ROWS 8192
#define KDIM 128
#define NPER 82          // int(8192 * 1 / 100) + 1
#define EPS  1.25e-3f    // certified |dot_hh - dot| bound coeff (x ||a||*||b||)

// Scratch (device globals: no allocation allowed)
__device__ float  g_r[ROWS];            // dot(x1_i, x2_i) / ||x2_i||
__device__ float  g_n1[ROWS];           // ||x1_i||
__device__ float  g_n2[ROWS];           // ||x2_j||
__device__ int    g_cb[ROWS];           // packed (cert<<16 | bord)
__device__ int    g_cnt[ROWS];          // final per-row count (or 0 / NPER marker)
__device__ int    g_flag[ROWS];         // flagged row list
__device__ int    g_nflag;              // number of flagged rows
__device__ __half g_x1h[ROWS * KDIM];   // fp16 rn of inputs
__device__ __half g_x2h[ROWS * KDIM];

__device__ __forceinline__ uint32_t smem_u32(const void* p) {
    uint32_t a;
    asm("{ .reg .u64 t; cvta.to.shared.u64 t, %1; cvt.u32.u64 %0, t; }"
        : "=r"(a) : "l"(p));
    return a;
}

#define LDSM_X4(r0, r1, r2, r3, addr) \
    asm volatile("ldmatrix.sync.aligned.m8n8.x4.shared.b16 {%0,%1,%2,%3}, [%4];" \
                 : "=r"(r0), "=r"(r1), "=r"(r2), "=r"(r3) : "r"(addr))

#define MMA_16816(c, a, b0, b1) \
    asm volatile("mma.sync.aligned.m16n8k16.row.col.f32.f16.f16.f32 " \
                 "{%0,%1,%2,%3}, {%4,%5,%6,%7}, {%8,%9}, {%0,%1,%2,%3};" \
                 : "+f"((c)[0]), "+f"((c)[1]), "+f"((c)[2]), "+f"((c)[3]) \
                 : "r"((a)[0]), "r"((a)[1]), "r"((a)[2]), "r"((a)[3]), \
                   "r"(b0), "r"(b1))

#define CP_ASYNC16(dst, src) \
    asm volatile("cp.async.cg.shared.global [%0], [%1], 16;" :: "r"(dst), "l"(src))
#define CP_ASYNC4(dst, src) \
    asm volatile("cp.async.ca.shared.global [%0], [%1], 4;" :: "r"(dst), "l"(src))
#define CP_COMMIT() asm volatile("cp.async.commit_group;" ::: "memory")

// ---------------------------------------------------------------------------
// Kernel A: thresholds + zero counters + fp16 conversion of both inputs.
// ---------------------------------------------------------------------------
__global__ void prep_kernel(const float* __restrict__ x1,
                            const float* __restrict__ x2) {
    int warp = (blockIdx.x * blockDim.x + threadIdx.x) >> 5;
    int lane = threadIdx.x & 31;
    if (warp >= ROWS) return;
    float4 a = *(const float4*)(x1 + warp * KDIM + lane * 4);
    float4 b = *(const float4*)(x2 + warp * KDIM + lane * 4);

    int base = warp * KDIM + lane * 4;
    {
        __half h0 = __float2half_rn(a.x), h1 = __float2half_rn(a.y);
        __half h2 = __float2half_rn(a.z), h3 = __float2half_rn(a.w);
        half2 H0 = __halves2half2(h0, h1), H1 = __halves2half2(h2, h3);
        *(uint2*)(g_x1h + base) = make_uint2(*(unsigned*)&H0, *(unsigned*)&H1);
    }
    {
        __half h0 = __float2half_rn(b.x), h1 = __float2half_rn(b.y);
        __half h2 = __float2half_rn(b.z), h3 = __float2half_rn(b.w);
        half2 H0 = __halves2half2(h0, h1), H1 = __halves2half2(h2, h3);
        *(uint2*)(g_x2h + base) = make_uint2(*(unsigned*)&H0, *(unsigned*)&H1);
    }

    float s1 = a.x * a.x + a.y * a.y + a.z * a.z + a.w * a.w;
    float s2 = b.x * b.x + b.y * b.y + b.z * b.z + b.w * b.w;
    float d  = a.x * b.x + a.y * b.y + a.z * b.z + a.w * b.w;
    #pragma unroll
    for (int o = 16; o > 0; o >>= 1) {
        s1 += __shfl_down_sync(0xffffffffu, s1, o);
        s2 += __shfl_down_sync(0xffffffffu, s2, o);
        d  += __shfl_down_sync(0xffffffffu, d,  o);
    }
    if (lane == 0) {
        float n2 = sqrtf(s2);
        g_n1[warp] = sqrtf(s1);
        g_n2[warp] = n2;
        g_r[warp]  = d / n2;
        g_cb[warp] = 0;
        if (warp == 0) g_nflag = 0;
    }
}

// ---------------------------------------------------------------------------
// Kernel B: hh-only counting GEMM, per row packed (cert<<16 | bord).
// Tile BM=128 x BN=128, 256 threads (8 warps, 2x4), warp tile 64x32.
// 2 CTAs/SM: 32 KB smem (double-buffered 16 KB chunks), <=128 regs.
// ---------------------------------------------------------------------------
#define CH 16384       // bytes per chunk buffer (A_hi 8K + B_hi 8K)

__device__ __forceinline__ void load_chunk(uint32_t bufb, int i0, int j0,
                                           int kc, int tid) {
    const int s  = tid & 3;
    const int rh = tid >> 2;           // 0..63
    const int swsh  = ((s ^ ((rh >> 1) & 3)) << 4);
    const int r2    = rh + 64;
    const int swsh2 = ((s ^ ((r2 >> 1) & 3)) << 4);
    CP_ASYNC16(bufb +        rh * 64 + swsh,  g_x1h + (i0 + rh) * KDIM + kc + s * 8);
    CP_ASYNC16(bufb +        r2 * 64 + swsh2, g_x1h + (i0 + r2) * KDIM + kc + s * 8);
    CP_ASYNC16(bufb + 8192 + rh * 64 + swsh,  g_x2h + (j0 + rh) * KDIM + kc + s * 8);
    CP_ASYNC16(bufb + 8192 + r2 * 64 + swsh2, g_x2h + (j0 + r2) * KDIM + kc + s * 8);
}

__device__ __forceinline__ void compute_chunk(uint32_t bufb, int wm, int wn,
                                              int l, float acc[4][4][4]) {
    const int lg = l >> 3, lr = l & 7;
    #pragma unroll
    for (int t = 0; t < 2; t++) {
        uint32_t ah[4][4];
        #pragma unroll
        for (int tm = 0; tm < 4; tm++) {
            const int row  = wm * 64 + tm * 16 + ((lg & 1) << 3) + lr;
            const int slot = 2 * t + (lg >> 1);
            const uint32_t off = row * 64 + ((slot ^ ((row >> 1) & 3)) << 4);
            LDSM_X4(ah[tm][0], ah[tm][1], ah[tm][2], ah[tm][3], bufb + off);
        }
        #pragma unroll
        for (int p = 0; p < 2; p++) {
            const int row  = wn * 32 + p * 16 + ((lg >> 1) << 3) + lr;
            const int slot = 2 * t + (lg & 1);
            const uint32_t off = row * 64 + ((slot ^ ((row >> 1) & 3)) << 4);
            uint32_t bh[4];
            LDSM_X4(bh[0], bh[1], bh[2], bh[3], bufb + 8192 + off);
            #pragma unroll
            for (int tm = 0; tm < 4; tm++) {
                MMA_16816(acc[tm][2 * p],     ah[tm], bh[0], bh[1]);
                MMA_16816(acc[tm][2 * p + 1], ah[tm], bh[2], bh[3]);
            }
        }
    }
}

__global__ __launch_bounds__(256, 2)
void pass1_kernel() {
    __shared__ char smem[2 * CH];
    const uint32_t sb = smem_u32(smem);
    const int tid = threadIdx.x;
    const int l   = tid & 31;
    const int wid = tid >> 5;        // 0..7
    const int wm  = wid >> 2;        // 0..1
    const int wn  = wid & 3;         // 0..3
    const int i0  = blockIdx.y * 128;
    const int j0  = blockIdx.x * 128;

    load_chunk(sb,      i0, j0, 0,  tid); CP_COMMIT();
    load_chunk(sb + CH, i0, j0, 32, tid); CP_COMMIT();

    float acc[4][4][4];
    #pragma unroll
    for (int a = 0; a < 4; a++)
        #pragma unroll
        for (int b = 0; b < 4; b++)
            #pragma unroll
            for (int c = 0; c < 4; c++) acc[a][b][c] = 0.f;

    #pragma unroll
    for (int c = 0; c < 4; c++) {
        if (c < 3) asm volatile("cp.async.wait_group 1;" ::: "memory");
        else       asm volatile("cp.async.wait_group 0;" ::: "memory");
        __syncthreads();
        compute_chunk(sb + (c & 1) * CH, wm, wn, l, acc);
        __syncthreads();
        if (c < 2) {
            load_chunk(sb + (c & 1) * CH, i0, j0, (c + 2) * 32, tid);
            CP_COMMIT();
        }
    }

    // Epilogue: per row, cert = #(m > eps), bord = #(|m| <= eps).
    float na[4], nb[4];
    #pragma unroll
    for (int tn = 0; tn < 4; tn++) {
        const int jb = j0 + wn * 32 + tn * 8 + ((l & 3) << 1);
        na[tn] = __ldg(&g_n2[jb]);
        nb[tn] = __ldg(&g_n2[jb + 1]);
    }

    #pragma unroll
    for (int tm = 0; tm < 4; tm++) {
        const int r0 = i0 + wm * 64 + tm * 16 + (l >> 2);
        const int r1 = r0 + 8;
        const float th0 = __ldg(&g_r[r0]);
        const float th1 = __ldg(&g_r[r1]);
        const float e0  = EPS * __ldg(&g_n1[r0]);
        const float e1  = EPS * __ldg(&g_n1[r1]);
        int p0 = 0, p1 = 0;        // packed (cert<<8 | bord)
        #pragma unroll
        for (int tn = 0; tn < 4; tn++) {
            #pragma unroll
            for (int q = 0; q < 4; q++) {
                const float er  = (q < 2) ? e0 : e1;
                const float th  = (q < 2) ? th0 : th1;
                const float nv  = (q & 1) ? nb[tn] : na[tn];
                const float m   = acc[tm][tn][q] - th * nv;
                const float eps = er * nv;
                int add = (m > eps) ? 256 : ((m >= -eps) ? 1 : 0);
                if (q < 2) p0 += add; else p1 += add;
            }
        }
        p0 += __shfl_xor_sync(0xffffffffu, p0, 1);
        p0 += __shfl_xor_sync(0xffffffffu, p0, 2);
        p1 += __shfl_xor_sync(0xffffffffu, p1, 1);
        p1 += __shfl_xor_sync(0xffffffffu, p1, 2);
        if ((l & 3) == 0) {
            atomicAdd(&g_cb[r0], ((p0 >> 8) << 16) | (p0 & 0xff));
            atomicAdd(&g_cb[r1], ((p1 >> 8) << 16) | (p1 & 0xff));
        }
    }
}

// ---------------------------------------------------------------------------
// Kernel C: decide rows; flag undecidable ones.
// ---------------------------------------------------------------------------
__global__ void flag_kernel() {
    int i = blockIdx.x * blockDim.x + threadIdx.x;
    if (i >= ROWS) return;
    const int cb   = g_cb[i];
    const int cert = cb >> 16;
    const int bord = cb & 0xffff;
    if (cert >= NPER) {
        g_cnt[i] = NPER;               // certainly rank >= NPER: indicator 0
    } else if (cert + bord < NPER) {
        g_cnt[i] = 0;                  // certainly rank < NPER: indicator 1
    } else {
        g_cnt[i] = 0;                  // refined exactly below
        int slot = atomicAdd(&g_nflag, 1);
        g_flag[slot] = i;
    }
}

// ---------------------------------------------------------------------------
// Kernel D: exact fp32 refinement of flagged rows; x1 row double-buffered
// via cp.async prefetch so the gmem latency is hidden behind the dot.
// ---------------------------------------------------------------------------
__global__ __launch_bounds__(128)
void refine_kernel(const float* __restrict__ x1, const float* __restrict__ x2) {
    __shared__ float rb[2][KDIM];
    const int tid = threadIdx.x;
    const int j   = blockIdx.x * 128 + tid;
    const float n2j = g_n2[j];
    const int nf = g_nflag;
    const uint32_t rb0 = smem_u32(&rb[0][tid]);
    const uint32_t rb1 = smem_u32(&rb[1][tid]);

    int f = blockIdx.y;
    if (f < nf) {
        CP_ASYNC4(rb0, x1 + g_flag[f] * KDIM + tid);
        CP_COMMIT();
    }
    int idx = 0;
    for (; f < nf; f += 16, idx ^= 1) {
        const int fn = f + 16;
        if (fn < nf) {
            CP_ASYNC4(idx ? rb0 : rb1, x1 + g_flag[fn] * KDIM + tid);
            CP_COMMIT();
            asm volatile("cp.async.wait_group 1;" ::: "memory");
        } else {
            asm volatile("cp.async.wait_group 0;" ::: "memory");
        }
        __syncthreads();
        const float* x1row = rb[idx];
        const int row = g_flag[f];
        const float4* pb = (const float4*)(x2 + j * KDIM);
        float s0 = 0.f, s1 = 0.f, s2 = 0.f, s3 = 0.f;
        #pragma unroll
        for (int k = 0; k < 32; k += 4) {
            float4 b0 = pb[k],     b1 = pb[k + 1];
            float4 b2 = pb[k + 2], b3 = pb[k + 3];
            const float* a0 = x1row + 4 * k;
            s0 += a0[0] * b0.x + a0[1] * b0.y + a0[2] * b0.z + a0[3] * b0.w;
            s1 += a0[4] * b1.x + a0[5] * b1.y + a0[6] * b1.z + a0[7] * b1.w;
            s2 += a0[8] * b2.x + a0[9] * b2.y + a0[10] * b2.z + a0[11] * b2.w;
            s3 += a0[12] * b3.x + a0[13] * b3.y + a0[14] * b3.z + a0[15] * b3.w;
        }
        const float s = (s0 + s1) + (s2 + s3);
        int c = (s > __ldg(&g_r[row]) * n2j && j != row) ? 1 : 0;
        #pragma unroll
        for (int o = 16; o > 0; o >>= 1) c += __shfl_xor_sync(0xffffffffu, c, o);
        if ((tid & 31) == 0 && c) atomicAdd(&g_cnt[row], c);
        __syncthreads();
    }
}

// ---------------------------------------------------------------------------
// Kernel E: mean of (count < NPER)
// ---------------------------------------------------------------------------
__global__ void finalize_kernel(float* __restrict__ out) {
    __shared__ int sh[1024];
    int t = threadIdx.x;
    int c = 0;
    for (int i = t; i < ROWS; i += 1024) c += (g_cnt[i] < NPER) ? 1 : 0;
    sh[t] = c;
    __syncthreads();
    #pragma unroll
    for (int s = 512; s > 0; s >>= 1) {
        if (t < s) sh[t] += sh[t + s];
        __syncthreads();
    }
    if (t == 0) out[0] = (float)sh[0] / (float)ROWS;
}

// ---------------------------------------------------------------------------
extern "C" void kernel_launch(void* const* d_in, const int* in_sizes, int n_in,
                              void* d_out, int out_size) {
    const float* x1 = (const float*)d_in[0];
    const float* x2 = (const float*)d_in[1];
    float* out = (float*)d_out;
    (void)in_sizes; (void)n_in; (void)out_size;

    prep_kernel<<<ROWS / 8, 256>>>(x1, x2);
    pass1_kernel<<<dim3(64, 64), 256>>>();
    flag_kernel<<<ROWS / 256, 256>>>();
    refine_kernel<<<dim3(64, 16), 128>>>(x1, x2);
    finalize_kernel<<<1, 1024>>>(out);
}